// round 10
// baseline (speedup 1.0000x reference)
#include <cuda_runtime.h>

// Single-node pitch loss: retire-fast compute + per-warp packed last-arriver.
//
// Grid 32 x 256 = 256 warps; each warp handles 4 contiguous 32-frame notes.
// Lane sub (0..7) of group grp (0..3) loads ONE float4 per track (warp spans
// 512B contiguous per track -> fully coalesced LDG.128), 3 width-8 shuffles
// reduce the gen-t difference, group leaders test |sum| > 0.5*len.
//
// Combine (no block barrier, no second node): REDUX.ADD collapses the warp's
// 4 hits; lane 0 issues ONE packed 64-bit atomicAdd into
//   g_acc = (hits << 32) | warps_done.
// Warps retire independently. The warp whose returned low word equals
// TOTAL_WARPS-1 is the last arriver and already holds the final hit total in
// the return value: it stores the loss and swaps g_acc back to 0. All 256
// adds are serialized by the L2 atomic unit before that return, so the reset
// is race-free; integer accumulation is order-independent -> bit-exact and
// deterministic across graph replays (g_acc self-resets every launch).
__device__ unsigned long long g_acc = 0ull;

__global__ void __launch_bounds__(256, 1)
pitch_loss_kernel(const float* __restrict__ gen_f0,
                  const float* __restrict__ t_f0,
                  const int*   __restrict__ onset,
                  const int*   __restrict__ offset,
                  float*       __restrict__ out,
                  int N, unsigned total_warps) {
    const int lane  = threadIdx.x & 31;
    const int sub   = lane & 7;                       // float4 slot in note
    const int grp   = lane >> 3;                      // which of warp's 4 notes
    const int gwarp = (blockIdx.x * blockDim.x + threadIdx.x) >> 5;
    const int note  = gwarp * 4 + grp;

    unsigned hit = 0;
    if (note < N) {
        const int a   = onset[note];
        const int b   = offset[note];
        const int len = b - a;

        float d;
        if (len == 32 && (a & 3) == 0) {
            // Fast path: one float4 per lane per track covers the segment.
            const float4 g = ((const float4*)(gen_f0 + a))[sub];
            const float4 t = ((const float4*)(t_f0  + a))[sub];
            d = ((g.x - t.x) + (g.y - t.y)) + ((g.z - t.z) + (g.w - t.w));
        } else {
            // General path: strided scalar loads over the segment.
            d = 0.0f;
            for (int i = a + sub; i < b; i += 8)
                d += gen_f0[i] - t_f0[i];
        }

        // Reduce within the 8-lane group (width = 8).
        #pragma unroll
        for (int o = 4; o > 0; o >>= 1)
            d += __shfl_down_sync(0xFFFFFFFFu, d, o, 8);

        hit = (sub == 0 && fabsf(d) > 0.5f * (float)len) ? 1u : 0u;
    }

    // Collapse the warp's 4 group hits (all 32 lanes participate; non-leaders
    // contribute 0). REDUX.ADD: single instruction, no shuffle chain.
    const unsigned whits = __reduce_add_sync(0xFFFFFFFFu, hit);

    if (lane == 0) {
        const unsigned long long contrib =
            ((unsigned long long)whits << 32) | 1ull;
        const unsigned long long old = atomicAdd(&g_acc, contrib);

        if ((unsigned)(old & 0xFFFFFFFFull) == total_warps - 1u) {
            const unsigned total = (unsigned)(old >> 32) + whits;
            out[0] = (float)total / (float)N;
            atomicExch(&g_acc, 0ull);   // reset for the next graph replay
        }
    }
}

extern "C" void kernel_launch(void* const* d_in, const int* in_sizes, int n_in,
                              void* d_out, int out_size) {
    const float* gen_f0 = (const float*)d_in[0];
    const float* t_f0   = (const float*)d_in[1];
    const int*   onset  = (const int*)d_in[2];
    const int*   offset = (const int*)d_in[3];
    float* out = (float*)d_out;

    const int N = in_sizes[2];   // number of notes (1024)

    const int THREADS = 256;                                  // 8 warps/block
    const int warps   = (N + 3) / 4;                          // 4 notes/warp
    const int blocks  = (warps * 32 + THREADS - 1) / THREADS; // 32
    const unsigned total_warps = (unsigned)(blocks * (THREADS / 32));

    pitch_loss_kernel<<<blocks, THREADS>>>(gen_f0, t_f0, onset, offset, out,
                                           N, total_warps);
}

// round 11
// speedup vs baseline: 1.0093x; 1.0093x over previous
#include <cuda_runtime.h>

// Single-node pitch loss: fire-and-forget REDG combine + one polling warp.
//
// Grid 32 x 256 = 256 warps; each warp handles 4 contiguous 32-frame notes.
// Lane sub (0..7) of group grp (0..3) loads ONE float4 per track (warp spans
// 512B contiguous per track -> coalesced LDG.128), 3 width-8 shuffles reduce
// the gen-t difference, group leaders test |sum| > 0.5*len (no division).
// REDUX.ADD collapses the warp's 4 hits; lane 0 issues ONE packed 64-bit
// atomicAdd into g_acc = (hits << 32) | warps_done with the RETURN UNUSED ->
// compiles to REDG (no-return reduction): workers retire immediately, no
// round-trip on their critical path (the R8 property, kept).
//
// Completion: exactly one warp (gwarp 0, lane 0) polls g_acc with
// atomicAdd(,0) until the low word reaches total_warps (all adds are
// serialized by the L2 atomic unit, so at that point the high word is the
// final hit total), plain-stores the loss, and swaps g_acc back to 0.
// Race-free, order-independent integer accumulation -> bit-exact and
// deterministic across graph replays (g_acc self-resets every launch).
// All 32 CTAs are co-resident (<< 148 SMs), so the spin cannot deadlock.
__device__ unsigned long long g_acc = 0ull;

__global__ void __launch_bounds__(256, 1)
pitch_loss_kernel(const float* __restrict__ gen_f0,
                  const float* __restrict__ t_f0,
                  const int*   __restrict__ onset,
                  const int*   __restrict__ offset,
                  float*       __restrict__ out,
                  int N, unsigned total_warps) {
    const int lane  = threadIdx.x & 31;
    const int sub   = lane & 7;                       // float4 slot in note
    const int grp   = lane >> 3;                      // which of warp's 4 notes
    const int gwarp = (blockIdx.x * blockDim.x + threadIdx.x) >> 5;
    const int note  = gwarp * 4 + grp;

    unsigned hit = 0;
    if (note < N) {
        const int a   = onset[note];
        const int b   = offset[note];
        const int len = b - a;

        float d;
        if (len == 32 && (a & 3) == 0) {
            // Fast path: one float4 per lane per track covers the segment.
            const float4 g = ((const float4*)(gen_f0 + a))[sub];
            const float4 t = ((const float4*)(t_f0  + a))[sub];
            d = ((g.x - t.x) + (g.y - t.y)) + ((g.z - t.z) + (g.w - t.w));
        } else {
            // General path: strided scalar loads over the segment.
            d = 0.0f;
            for (int i = a + sub; i < b; i += 8)
                d += gen_f0[i] - t_f0[i];
        }

        // Reduce within the 8-lane group (width = 8).
        #pragma unroll
        for (int o = 4; o > 0; o >>= 1)
            d += __shfl_down_sync(0xFFFFFFFFu, d, o, 8);

        hit = (sub == 0 && fabsf(d) > 0.5f * (float)len) ? 1u : 0u;
    }

    // One REDUX.ADD collapses the warp's hits (non-leaders contribute 0).
    const unsigned whits = __reduce_add_sync(0xFFFFFFFFu, hit);

    if (lane == 0) {
        // Fire-and-forget: return unused -> REDG. Workers retire immediately.
        atomicAdd(&g_acc, ((unsigned long long)whits << 32) | 1ull);

        // Dedicated completion warp: poll until all warps' adds have landed,
        // then publish the loss and reset the accumulator.
        if (gwarp == 0) {
            unsigned long long v;
            do {
                v = atomicAdd(&g_acc, 0ull);   // ordered read of g_acc
            } while ((unsigned)(v & 0xFFFFFFFFull) != total_warps);
            out[0] = (float)(unsigned)(v >> 32) / (float)N;
            atomicExch(&g_acc, 0ull);          // reset for the next replay
        }
    }
}

extern "C" void kernel_launch(void* const* d_in, const int* in_sizes, int n_in,
                              void* d_out, int out_size) {
    const float* gen_f0 = (const float*)d_in[0];
    const float* t_f0   = (const float*)d_in[1];
    const int*   onset  = (const int*)d_in[2];
    const int*   offset = (const int*)d_in[3];
    float* out = (float*)d_out;

    const int N = in_sizes[2];   // number of notes (1024)

    const int THREADS = 256;                                  // 8 warps/block
    const int warps   = (N + 3) / 4;                          // 4 notes/warp
    const int blocks  = (warps * 32 + THREADS - 1) / THREADS; // 32
    const unsigned total_warps = (unsigned)(blocks * (THREADS / 32));

    pitch_loss_kernel<<<blocks, THREADS>>>(gen_f0, t_f0, onset, offset, out,
                                           N, total_warps);
}

// round 13
// speedup vs baseline: 1.0640x; 1.0542x over previous
#include <cuda_runtime.h>

// Pitch loss: memset node for zero-init + one retire-fast kernel with
// speculative parallel loads.
//
// Grid 32 x 256 = 256 warps; each warp handles 4 notes via 8-lane groups.
// The expected layout (note k = frames [32k, 32k+32)) is SPECULATED so the
// float4 f0 loads issue in parallel with the onset/offset loads -- no serial
// index->data dependency on the critical path. The fast result commits only
// if the loaded indices confirm the speculation; otherwise a general strided
// path recomputes from the real segment (correct for any input).
//
// Per note: one LDG.128 per lane per track (warp spans 512B contiguous per
// track -> fully coalesced), 3 width-8 shuffles reduce the gen-t difference,
// group leader tests |sum| > 0.5*len (no division) and, only on a hit, fires
// atomicAdd(out, 1/N) with the return UNUSED -> compiles to REDG: no round
// trip, no completion tail, warps retire immediately. No __syncthreads, no
// device scratch, no polling (R12's weak-load poll was the correctness bug
// class; all completion-detection variants cost >= the node tax anyway).
//
// Determinism: contributions are exactly 2^-10; all partial sums m/1024
// (m <= 1024) are exactly representable in fp32 -> order-independent,
// bit-exact across graph replays. d_out is zeroed by a memset node ordered
// before the kernel in the same stream.
__global__ void __launch_bounds__(256, 1)
pitch_loss_kernel(const float* __restrict__ gen_f0,
                  const float* __restrict__ t_f0,
                  const int*   __restrict__ onset,
                  const int*   __restrict__ offset,
                  float*       __restrict__ out,
                  int N) {
    const int lane  = threadIdx.x & 31;
    const int sub   = lane & 7;                       // float4 slot in note
    const int grp   = lane >> 3;                      // which of warp's 4 notes
    const int gwarp = (blockIdx.x * blockDim.x + threadIdx.x) >> 5;
    const int note  = gwarp * 4 + grp;

    if (note >= N) return;

    // Speculative fast-path loads: issue immediately, in parallel with the
    // index loads below (no dependency). In-bounds for the expected layout.
    const int spec_a = note * 32;
    const float4 g = ((const float4*)(gen_f0 + spec_a))[sub];
    const float4 t = ((const float4*)(t_f0  + spec_a))[sub];

    const int a   = onset[note];
    const int b   = offset[note];
    const int len = b - a;

    float d;
    if (a == spec_a && len == 32) {
        // Speculation confirmed: the float4s cover exactly [a, a+32).
        d = ((g.x - t.x) + (g.y - t.y)) + ((g.z - t.z) + (g.w - t.w));
    } else {
        // Speculation failed: general strided path over the real segment.
        d = 0.0f;
        for (int i = a + sub; i < b; i += 8)
            d += gen_f0[i] - t_f0[i];
    }

    // Reduce within the 8-lane group (width = 8).
    #pragma unroll
    for (int o = 4; o > 0; o >>= 1)
        d += __shfl_down_sync(0xFFFFFFFFu, d, o, 8);

    // Group leader: predicated fire-and-forget reduction into the output.
    if (sub == 0 && fabsf(d) > 0.5f * (float)len)
        atomicAdd(out, 1.0f / (float)N);   // return unused -> REDG
}

extern "C" void kernel_launch(void* const* d_in, const int* in_sizes, int n_in,
                              void* d_out, int out_size) {
    const float* gen_f0 = (const float*)d_in[0];
    const float* t_f0   = (const float*)d_in[1];
    const int*   onset  = (const int*)d_in[2];
    const int*   offset = (const int*)d_in[3];
    float* out = (float*)d_out;

    const int N = in_sizes[2];   // number of notes (1024)

    // Zero the scalar output with a memset node (graph-capturable, async,
    // same stream -> ordered before the kernel's reductions).
    cudaMemsetAsync(out, 0, sizeof(float));

    const int THREADS = 256;                                  // 8 warps/block
    const int warps   = (N + 3) / 4;                          // 4 notes/warp
    const int blocks  = (warps * 32 + THREADS - 1) / THREADS; // 32
    pitch_loss_kernel<<<blocks, THREADS>>>(gen_f0, t_f0, onset, offset, out, N);
}